// round 15
// baseline (speedup 1.0000x reference)
#include <cuda_runtime.h>
#include <cstdint>

// Problem dims
#define T_STEPS 256
#define BATCH   128
#define INDIM   1024
#define HID     1024
#define OUTDIM  256
#define MROWS   (T_STEPS * BATCH)   // 32768
#define BETA_F  0.9f
#define KC      512                 // Eigen gebp panel depth (bit-exactness contract)

// Scratch (allocation-free rule: __device__ globals)
__device__ float g_cur1[(size_t)MROWS * HID];     // 128 MB
__device__ float g_cur2[(size_t)MROWS * OUTDIM];  // 32 MB
__device__ float g_xT  [(size_t)INDIM * MROWS];   // 128 MB  x transposed (k-major)
__device__ float g_w1T [(size_t)INDIM * HID];     // 4 MB    w1 transposed
__device__ float g_w2T [(size_t)HID * OUTDIM];    // 1 MB    w2 transposed

typedef unsigned long long ull;

// ---- packed f32x2 helpers (each lane = independent IEEE fp32 rn op) --------
__device__ __forceinline__ void ffma2(ull& d, ull a, ull b) {
    asm("fma.rn.f32x2 %0, %1, %2, %0;" : "+l"(d) : "l"(a), "l"(b));
}
__device__ __forceinline__ ull bcast2(float x) {
    ull r; asm("mov.b64 %0, {%1, %1};" : "=l"(r) : "f"(x)); return r;
}
__device__ __forceinline__ void unpack2(float& lo, float& hi, ull v) {
    asm("mov.b64 {%0, %1}, %2;" : "=f"(lo), "=f"(hi) : "l"(v));
}

// ---- cp.async helpers ------------------------------------------------------
__device__ __forceinline__ void cp_async16(uint32_t smem, const void* g) {
    asm volatile("cp.async.cg.shared.global [%0], [%1], 16;" :: "r"(smem), "l"(g));
}
__device__ __forceinline__ void cp_commit() {
    asm volatile("cp.async.commit_group;" ::: "memory");
}
template<int N>
__device__ __forceinline__ void cp_wait() {
    asm volatile("cp.async.wait_group %0;" :: "n"(N) : "memory");
}

// ---------------------------------------------------------------------------
// Vectorized tiled transpose: in [rows][cols] -> out [cols][rows]. Bit copy.
// 32x32 tile, 256 threads, one LDG.128 + one STG.128 per thread.
// ---------------------------------------------------------------------------
__global__ void transpose_v4(const float* __restrict__ in, float* __restrict__ out,
                             int rows, int cols)
{
    __shared__ float tile[32][33];
    const int c0 = blockIdx.x * 32;
    const int r0 = blockIdx.y * 32;
    const int tr = threadIdx.x >> 3;          // 0..31
    const int tc = (threadIdx.x & 7) << 2;    // 0,4,...,28

    float4 v = *reinterpret_cast<const float4*>(&in[(size_t)(r0 + tr) * cols + c0 + tc]);
    tile[tr][tc + 0] = v.x; tile[tr][tc + 1] = v.y;
    tile[tr][tc + 2] = v.z; tile[tr][tc + 3] = v.w;
    __syncthreads();

    float4 o;
    o.x = tile[tc + 0][tr]; o.y = tile[tc + 1][tr];
    o.z = tile[tc + 2][tr]; o.w = tile[tc + 3][tr];
    *reinterpret_cast<float4*>(&out[(size_t)(c0 + tr) * rows + r0 + tc]) = o;
}

#define BK 32
#define NITERF (INDIM / BK)   // 32 iterations over full K=1024
#define FOLD_ITER (KC / BK - 1)  // 15: after this iter's compute, panel 1 ends
#define BM1 64
#define BN1 128

// ---------------------------------------------------------------------------
// GEMM1 FUSED full-K (both kc=512 panels, serial in one kernel):
// A,B k-major, cp.async, 2-stage, BK=32, 64x128 tile, 128 threads, 4 CTAs/SM.
// Numerics contract (bit-match Eigen gebp kc=512, VERIFIED rel_err==0):
//   chain(k=0..511) is STG'd raw to C at the panel boundary (exact bits,
//   exactly as the former phase-0 kernel did), acc reset; at the end
//   C = fadd( fadd(C_partial, chain(k=512..1023)), bias ).
// Per-element op sequence identical to the verified split-kernel contract.
// Microtile 8m(4 f32x2 m-pairs) x 8n per thread.
// ---------------------------------------------------------------------------
__global__ __launch_bounds__(128, 4)
void sgemm1_fused(const float* __restrict__ A,
                  const float* __restrict__ B,
                  const float* __restrict__ bias,
                  float* __restrict__ C,
                  int lda, int ldb, int N)
{
    __shared__ __align__(16) float As[2][BK][BM1];   // 16 KB
    __shared__ __align__(16) float Bs[2][BK][BN1];   // 32 KB

    const int tid = threadIdx.x;
    const int bm = blockIdx.y * BM1;
    const int bn = blockIdx.x * BN1;

    const int tx = (tid & 15) << 2;   // n base (4 wide); second group at +64
    const int ty = (tid >> 4) << 3;   // m base (8 tall, consecutive)

    const int lkA  = tid >> 4;          // 0..7
    const int lofA = (tid & 15) << 2;   // 0..60
    const int lkB  = tid >> 5;          // 0..3
    const int lofB = (tid & 31) << 2;   // 0..124

    const uint32_t sA = (uint32_t)__cvta_generic_to_shared(&As[0][0][0]);
    const uint32_t sB = (uint32_t)__cvta_generic_to_shared(&Bs[0][0][0]);
    #define SA_ADDR(b, k, off) (sA + (uint32_t)(((b) * BK + (k)) * BM1 + (off)) * 4u)
    #define SB_ADDR(b, k, off) (sB + (uint32_t)(((b) * BK + (k)) * BN1 + (off)) * 4u)

    ull acc[4][8];
    #pragma unroll
    for (int i = 0; i < 4; i++)
        #pragma unroll
        for (int j = 0; j < 8; j++) acc[i][j] = 0ull;

    // prologue
    #pragma unroll
    for (int r = 0; r < BK; r += 8)
        cp_async16(SA_ADDR(0, lkA + r, lofA), &A[(size_t)(lkA + r) * lda + bm + lofA]);
    #pragma unroll
    for (int r = 0; r < BK; r += 4)
        cp_async16(SB_ADDR(0, lkB + r, lofB), &B[(size_t)(lkB + r) * ldb + bn + lofB]);
    cp_commit();
    cp_wait<0>();
    __syncthreads();

    int buf = 0;
    for (int iter = 0; iter < NITERF; iter++) {
        if (iter + 1 < NITERF) {
            const int kt = (iter + 1) * BK;
            const int nb = buf ^ 1;
            #pragma unroll
            for (int r = 0; r < BK; r += 8)
                cp_async16(SA_ADDR(nb, lkA + r, lofA), &A[(size_t)(kt + lkA + r) * lda + bm + lofA]);
            #pragma unroll
            for (int r = 0; r < BK; r += 4)
                cp_async16(SB_ADDR(nb, lkB + r, lofB), &B[(size_t)(kt + lkB + r) * ldb + bn + lofB]);
            cp_commit();
        }

        #pragma unroll
        for (int k = 0; k < BK; k++) {
            ulonglong2 av0 = *reinterpret_cast<const ulonglong2*>(&As[buf][k][ty]);
            ulonglong2 av1 = *reinterpret_cast<const ulonglong2*>(&As[buf][k][ty + 4]);
            float4 b0 = *reinterpret_cast<const float4*>(&Bs[buf][k][tx]);
            float4 b1 = *reinterpret_cast<const float4*>(&Bs[buf][k][tx + 64]);
            ull ap[4] = {av0.x, av0.y, av1.x, av1.y};
            ull bb[8];
            bb[0] = bcast2(b0.x); bb[1] = bcast2(b0.y);
            bb[2] = bcast2(b0.z); bb[3] = bcast2(b0.w);
            bb[4] = bcast2(b1.x); bb[5] = bcast2(b1.y);
            bb[6] = bcast2(b1.z); bb[7] = bcast2(b1.w);
            #pragma unroll
            for (int i = 0; i < 4; i++)
                #pragma unroll
                for (int j = 0; j < 8; j++)
                    ffma2(acc[i][j], ap[i], bb[j]);
        }

        // panel boundary: stash chain-0 partial to C (raw bits), reset acc
        if (iter == FOLD_ITER) {
            #pragma unroll
            for (int i = 0; i < 4; i++) {
                float lo[8], hi[8];
                #pragma unroll
                for (int j = 0; j < 8; j++) {
                    unpack2(lo[j], hi[j], acc[i][j]);
                    acc[i][j] = 0ull;
                }
                int r0 = bm + ty + 2 * i;
                float4 s0 = {lo[0], lo[1], lo[2], lo[3]};
                float4 s1 = {lo[4], lo[5], lo[6], lo[7]};
                float4 s2 = {hi[0], hi[1], hi[2], hi[3]};
                float4 s3 = {hi[4], hi[5], hi[6], hi[7]};
                *reinterpret_cast<float4*>(&C[(size_t)r0 * N + bn + tx]) = s0;
                *reinterpret_cast<float4*>(&C[(size_t)r0 * N + bn + tx + 64]) = s1;
                *reinterpret_cast<float4*>(&C[(size_t)(r0 + 1) * N + bn + tx]) = s2;
                *reinterpret_cast<float4*>(&C[(size_t)(r0 + 1) * N + bn + tx + 64]) = s3;
            }
        }

        if (iter + 1 < NITERF) {
            cp_wait<0>();
            __syncthreads();
            buf ^= 1;
        }
    }

    // epilogue: C = fadd( fadd(partial, chain1), bias )
    {
        float4 bv0 = *reinterpret_cast<const float4*>(&bias[bn + tx]);
        float4 bv1 = *reinterpret_cast<const float4*>(&bias[bn + tx + 64]);
        const float bb[8] = {bv0.x, bv0.y, bv0.z, bv0.w, bv1.x, bv1.y, bv1.z, bv1.w};
        #pragma unroll
        for (int i = 0; i < 4; i++) {
            #pragma unroll
            for (int half = 0; half < 2; half++) {
                int row = bm + ty + 2 * i + half;
                float4 p0 = *reinterpret_cast<const float4*>(&C[(size_t)row * N + bn + tx]);
                float4 p1 = *reinterpret_cast<const float4*>(&C[(size_t)row * N + bn + tx + 64]);
                float pr[8] = {p0.x, p0.y, p0.z, p0.w, p1.x, p1.y, p1.z, p1.w};
                float o[8];
                #pragma unroll
                for (int j = 0; j < 8; j++) {
                    float lo, hi;
                    unpack2(lo, hi, acc[i][j]);
                    float mine = half ? hi : lo;
                    o[j] = __fadd_rn(__fadd_rn(pr[j], mine), bb[j]);
                }
                float4 s0 = {o[0], o[1], o[2], o[3]};
                float4 s1 = {o[4], o[5], o[6], o[7]};
                *reinterpret_cast<float4*>(&C[(size_t)row * N + bn + tx]) = s0;
                *reinterpret_cast<float4*>(&C[(size_t)row * N + bn + tx + 64]) = s1;
            }
        }
    }
    #undef SA_ADDR
    #undef SB_ADDR
}

// ---------------------------------------------------------------------------
// GEMM2 FUSED full-K: same serial-panel scheme; A m-major (spk1, LDG+STS
// staged), B k-major (w2T, cp.async). 64x128 tile, 128 threads, 4 CTAs/SM.
// Same per-element numerics contract.
// ---------------------------------------------------------------------------
__global__ __launch_bounds__(128, 4)
void sgemm2_fused(const float* __restrict__ A,
                  const float* __restrict__ B,
                  const float* __restrict__ bias,
                  float* __restrict__ C,
                  int lda, int ldb, int N)
{
    __shared__ __align__(16) float As[2][BK][BM1];   // 16 KB
    __shared__ __align__(16) float Bs[2][BK][BN1];   // 32 KB

    const int tid = threadIdx.x;
    const int bm = blockIdx.y * BM1;
    const int bn = blockIdx.x * BN1;

    const int tx = (tid & 15) << 2;
    const int ty = (tid >> 4) << 3;

    const int lkB  = tid >> 5;          // 0..3
    const int lofB = (tid & 31) << 2;   // 0..124

    const int lr2  = tid >> 1;          // 0..63
    const int lc16 = (tid & 1) << 4;    // 0, 16

    const uint32_t sB = (uint32_t)__cvta_generic_to_shared(&Bs[0][0][0]);
    #define SB2_ADDR(b, k, off) (sB + (uint32_t)(((b) * BK + (k)) * BN1 + (off)) * 4u)

    ull acc[4][8];
    #pragma unroll
    for (int i = 0; i < 4; i++)
        #pragma unroll
        for (int j = 0; j < 8; j++) acc[i][j] = 0ull;

    // prologue
    #pragma unroll
    for (int r = 0; r < BK; r += 4)
        cp_async16(SB2_ADDR(0, lkB + r, lofB), &B[(size_t)(lkB + r) * ldb + bn + lofB]);
    #pragma unroll
    for (int q = 0; q < 4; q++) {
        float4 a = *reinterpret_cast<const float4*>(&A[(size_t)(bm + lr2) * lda + lc16 + 4 * q]);
        As[0][lc16 + 4 * q + 0][lr2] = a.x;
        As[0][lc16 + 4 * q + 1][lr2] = a.y;
        As[0][lc16 + 4 * q + 2][lr2] = a.z;
        As[0][lc16 + 4 * q + 3][lr2] = a.w;
    }
    cp_commit();
    cp_wait<0>();
    __syncthreads();

    int buf = 0;
    for (int iter = 0; iter < NITERF; iter++) {
        float4 stA[4];
        if (iter + 1 < NITERF) {
            const int kt = (iter + 1) * BK;
            const int nb = buf ^ 1;
            #pragma unroll
            for (int r = 0; r < BK; r += 4)
                cp_async16(SB2_ADDR(nb, lkB + r, lofB), &B[(size_t)(kt + lkB + r) * ldb + bn + lofB]);
            #pragma unroll
            for (int q = 0; q < 4; q++)
                stA[q] = *reinterpret_cast<const float4*>(&A[(size_t)(bm + lr2) * lda + kt + lc16 + 4 * q]);
            cp_commit();
        }

        #pragma unroll
        for (int k = 0; k < BK; k++) {
            ulonglong2 av0 = *reinterpret_cast<const ulonglong2*>(&As[buf][k][ty]);
            ulonglong2 av1 = *reinterpret_cast<const ulonglong2*>(&As[buf][k][ty + 4]);
            float4 b0 = *reinterpret_cast<const float4*>(&Bs[buf][k][tx]);
            float4 b1 = *reinterpret_cast<const float4*>(&Bs[buf][k][tx + 64]);
            ull ap[4] = {av0.x, av0.y, av1.x, av1.y};
            ull bb[8];
            bb[0] = bcast2(b0.x); bb[1] = bcast2(b0.y);
            bb[2] = bcast2(b0.z); bb[3] = bcast2(b0.w);
            bb[4] = bcast2(b1.x); bb[5] = bcast2(b1.y);
            bb[6] = bcast2(b1.z); bb[7] = bcast2(b1.w);
            #pragma unroll
            for (int i = 0; i < 4; i++)
                #pragma unroll
                for (int j = 0; j < 8; j++)
                    ffma2(acc[i][j], ap[i], bb[j]);
        }

        // panel boundary: stash chain-0 partial to C (raw bits), reset acc
        if (iter == FOLD_ITER) {
            #pragma unroll
            for (int i = 0; i < 4; i++) {
                float lo[8], hi[8];
                #pragma unroll
                for (int j = 0; j < 8; j++) {
                    unpack2(lo[j], hi[j], acc[i][j]);
                    acc[i][j] = 0ull;
                }
                int r0 = bm + ty + 2 * i;
                float4 s0 = {lo[0], lo[1], lo[2], lo[3]};
                float4 s1 = {lo[4], lo[5], lo[6], lo[7]};
                float4 s2 = {hi[0], hi[1], hi[2], hi[3]};
                float4 s3 = {hi[4], hi[5], hi[6], hi[7]};
                *reinterpret_cast<float4*>(&C[(size_t)r0 * N + bn + tx]) = s0;
                *reinterpret_cast<float4*>(&C[(size_t)r0 * N + bn + tx + 64]) = s1;
                *reinterpret_cast<float4*>(&C[(size_t)(r0 + 1) * N + bn + tx]) = s2;
                *reinterpret_cast<float4*>(&C[(size_t)(r0 + 1) * N + bn + tx + 64]) = s3;
            }
        }

        if (iter + 1 < NITERF) {
            const int nb = buf ^ 1;
            #pragma unroll
            for (int q = 0; q < 4; q++) {
                As[nb][lc16 + 4 * q + 0][lr2] = stA[q].x;
                As[nb][lc16 + 4 * q + 1][lr2] = stA[q].y;
                As[nb][lc16 + 4 * q + 2][lr2] = stA[q].z;
                As[nb][lc16 + 4 * q + 3][lr2] = stA[q].w;
            }
            cp_wait<0>();
            __syncthreads();
            buf = nb;
        }
    }

    // epilogue: C = fadd( fadd(partial, chain1), bias )
    {
        float4 bv0 = *reinterpret_cast<const float4*>(&bias[bn + tx]);
        float4 bv1 = *reinterpret_cast<const float4*>(&bias[bn + tx + 64]);
        const float bb[8] = {bv0.x, bv0.y, bv0.z, bv0.w, bv1.x, bv1.y, bv1.z, bv1.w};
        #pragma unroll
        for (int i = 0; i < 4; i++) {
            #pragma unroll
            for (int half = 0; half < 2; half++) {
                int row = bm + ty + 2 * i + half;
                float4 p0 = *reinterpret_cast<const float4*>(&C[(size_t)row * N + bn + tx]);
                float4 p1 = *reinterpret_cast<const float4*>(&C[(size_t)row * N + bn + tx + 64]);
                float pr[8] = {p0.x, p0.y, p0.z, p0.w, p1.x, p1.y, p1.z, p1.w};
                float o[8];
                #pragma unroll
                for (int j = 0; j < 8; j++) {
                    float lo, hi;
                    unpack2(lo, hi, acc[i][j]);
                    float mine = half ? hi : lo;
                    o[j] = __fadd_rn(__fadd_rn(pr[j], mine), bb[j]);
                }
                float4 s0 = {o[0], o[1], o[2], o[3]};
                float4 s1 = {o[4], o[5], o[6], o[7]};
                *reinterpret_cast<float4*>(&C[(size_t)row * N + bn + tx]) = s0;
                *reinterpret_cast<float4*>(&C[(size_t)row * N + bn + tx + 64]) = s1;
            }
        }
    }
    #undef SB2_ADDR
}

// ---------------------------------------------------------------------------
// LIF recurrence, XLA-exact op ordering per lane (no FMA contraction).
// Scalar, one neuron per thread, next-t prefetch (R10-proven).
// ---------------------------------------------------------------------------
__device__ __forceinline__ void lif_step(float& mem, float& s, float c, float thr) {
    float t0 = __fmul_rn(BETA_F, mem);
    float t1 = __fadd_rn(t0, c);
    float t2 = __fmul_rn(s, thr);
    mem = __fsub_rn(t1, t2);
    s = (__fsub_rn(mem, thr) > 0.f) ? 1.0f : 0.0f;
}

__global__ void lif_scan1(const float* __restrict__ cur,
                          const float* __restrict__ thr_p,
                          float* __restrict__ spk_rec,
                          int stride)
{
    const int idx = blockIdx.x * blockDim.x + threadIdx.x;
    const float thr = *thr_p;
    float mem = 0.f, s = 0.f;
    const float* p = cur + idx;
    float* q = spk_rec + idx;
    float c = p[0];
    #pragma unroll 8
    for (int t = 0; t < T_STEPS; t++) {
        float cn = 0.f;
        if (t + 1 < T_STEPS) cn = p[(size_t)(t + 1) * stride];
        lif_step(mem, s, c, thr);
        q[(size_t)t * stride] = s;
        c = cn;
    }
}

// ---------------------------------------------------------------------------
extern "C" void kernel_launch(void* const* d_in, const int* in_sizes, int n_in,
                              void* d_out, int out_size)
{
    const float* x    = (const float*)d_in[0];  // [T,B,I]
    const float* w1   = (const float*)d_in[1];  // [H,I]
    const float* b1   = (const float*)d_in[2];  // [H]
    const float* w2   = (const float*)d_in[3];  // [O,H]
    const float* b2   = (const float*)d_in[4];  // [O]
    const float* thr1 = (const float*)d_in[5];  // scalar
    const float* thr2 = (const float*)d_in[6];  // scalar

    float* out  = (float*)d_out;
    float* spk1 = out;                                    // [T,B,H]
    float* spk2 = out + (size_t)T_STEPS * BATCH * HID;    // [T,B,O]

    float *cur1, *cur2, *xT, *w1T, *w2T;
    cudaGetSymbolAddress((void**)&cur1, g_cur1);
    cudaGetSymbolAddress((void**)&cur2, g_cur2);
    cudaGetSymbolAddress((void**)&xT,  g_xT);
    cudaGetSymbolAddress((void**)&w1T, g_w1T);
    cudaGetSymbolAddress((void**)&w2T, g_w2T);

    // prep: bit-copy transposes to k-major layouts (launch idx 0-2;
    // fused GEMM1 lands at idx 3 = the ncu capture slot)
    transpose_v4<<<dim3(INDIM / 32, MROWS / 32), 256>>>(x, xT, MROWS, INDIM);
    transpose_v4<<<dim3(INDIM / 32, HID / 32), 256>>>(w1, w1T, HID, INDIM);
    transpose_v4<<<dim3(HID / 32, OUTDIM / 32), 256>>>(w2, w2T, OUTDIM, HID);

    // 1) cur1 = X @ W1^T + b1   (fused serial panels, 64x128 CTAs, 4/SM)
    {
        dim3 grid(HID / BN1, MROWS / BM1);   // (8, 512) = 4096 CTAs
        sgemm1_fused<<<grid, 128>>>(xT, w1T, b1, cur1, MROWS, HID, HID);
    }
    // 2) LIF layer 1 -> spk1_rec
    lif_scan1<<<(BATCH * HID) / 256, 256>>>(cur1, thr1, spk1, BATCH * HID);

    // 3) cur2 = spk1_rec @ W2^T + b2   (fused serial panels)
    {
        dim3 grid(OUTDIM / BN1, MROWS / BM1);  // (2, 512) = 1024 CTAs
        sgemm2_fused<<<grid, 128>>>(spk1, w2T, b2, cur2, HID, OUTDIM, OUTDIM);
    }
    // 4) LIF layer 2 -> spk2_rec
    lif_scan1<<<(BATCH * OUTDIM) / 256, 256>>>(cur2, thr2, spk2, BATCH * OUTDIM);
}

// round 16
// speedup vs baseline: 1.0135x; 1.0135x over previous
#include <cuda_runtime.h>
#include <cstdint>

// Problem dims
#define T_STEPS 256
#define BATCH   128
#define INDIM   1024
#define HID     1024
#define OUTDIM  256
#define MROWS   (T_STEPS * BATCH)   // 32768
#define BETA_F  0.9f
#define KC      512                 // Eigen gebp panel depth (bit-exactness contract)

// Scratch (allocation-free rule: __device__ globals)
__device__ float g_cur1[(size_t)MROWS * HID];     // 128 MB
__device__ float g_cur2[(size_t)MROWS * OUTDIM];  // 32 MB
__device__ float g_xT  [(size_t)INDIM * MROWS];   // 128 MB  x transposed (k-major)
__device__ float g_w1T [(size_t)INDIM * HID];     // 4 MB    w1 transposed
__device__ float g_w2T [(size_t)HID * OUTDIM];    // 1 MB    w2 transposed

typedef unsigned long long ull;

// ---- packed f32x2 helpers (each lane = independent IEEE fp32 rn op) --------
__device__ __forceinline__ void ffma2(ull& d, ull a, ull b) {
    asm("fma.rn.f32x2 %0, %1, %2, %0;" : "+l"(d) : "l"(a), "l"(b));
}
__device__ __forceinline__ ull bcast2(float x) {
    ull r; asm("mov.b64 %0, {%1, %1};" : "=l"(r) : "f"(x)); return r;
}
__device__ __forceinline__ void unpack2(float& lo, float& hi, ull v) {
    asm("mov.b64 {%0, %1}, %2;" : "=f"(lo), "=f"(hi) : "l"(v));
}

// ---- cp.async helpers ------------------------------------------------------
__device__ __forceinline__ void cp_async16(uint32_t smem, const void* g) {
    asm volatile("cp.async.cg.shared.global [%0], [%1], 16;" :: "r"(smem), "l"(g));
}
__device__ __forceinline__ void cp_commit() {
    asm volatile("cp.async.commit_group;" ::: "memory");
}
template<int N>
__device__ __forceinline__ void cp_wait() {
    asm volatile("cp.async.wait_group %0;" :: "n"(N) : "memory");
}

// ---------------------------------------------------------------------------
// Vectorized tiled transpose: in [rows][cols] -> out [cols][rows]. Bit copy.
// 32x32 tile, 256 threads, one LDG.128 + one STG.128 per thread.
// ---------------------------------------------------------------------------
__global__ void transpose_v4(const float* __restrict__ in, float* __restrict__ out,
                             int rows, int cols)
{
    __shared__ float tile[32][33];
    const int c0 = blockIdx.x * 32;
    const int r0 = blockIdx.y * 32;
    const int tr = threadIdx.x >> 3;          // 0..31
    const int tc = (threadIdx.x & 7) << 2;    // 0,4,...,28

    float4 v = *reinterpret_cast<const float4*>(&in[(size_t)(r0 + tr) * cols + c0 + tc]);
    tile[tr][tc + 0] = v.x; tile[tr][tc + 1] = v.y;
    tile[tr][tc + 2] = v.z; tile[tr][tc + 3] = v.w;
    __syncthreads();

    float4 o;
    o.x = tile[tc + 0][tr]; o.y = tile[tc + 1][tr];
    o.z = tile[tc + 2][tr]; o.w = tile[tc + 3][tr];
    *reinterpret_cast<float4*>(&out[(size_t)(c0 + tr) * rows + r0 + tc]) = o;
}

#define BK 32
#define NITER (KC / BK)   // 16
#define BM1 64
#define BN1 128

// ---------------------------------------------------------------------------
// GEMM1 panel (kc=512): A,B k-major, cp.async, 2-stage, BK=32.
// R13/R14-PROVEN: 64x128 tile, 128 threads, 4 CTAs/SM (504us/phase, fma=85%).
// Numerics contract (bit-match Eigen gebp kc=512, VERIFIED rel_err==0):
//   per element: S = fadd( chain(k=0..511), chain(k=512..1023) ), chains are
//   ascending-k fp32 FMA chains from 0; then ONE rounded bias add (phase 1).
// Microtile 8m(4 f32x2 m-pairs) x 8n per thread.
// ---------------------------------------------------------------------------
__global__ __launch_bounds__(128, 4)
void sgemm1_panel(const float* __restrict__ A,
                  const float* __restrict__ B,
                  const float* __restrict__ bias,
                  float* __restrict__ C,
                  int lda, int ldb, int N, int addBias)
{
    __shared__ __align__(16) float As[2][BK][BM1];   // 16 KB
    __shared__ __align__(16) float Bs[2][BK][BN1];   // 32 KB

    const int tid = threadIdx.x;
    const int bm = blockIdx.y * BM1;
    const int bn = blockIdx.x * BN1;

    const int tx = (tid & 15) << 2;   // n base (4 wide); second group at +64
    const int ty = (tid >> 4) << 3;   // m base (8 tall, consecutive)

    const int lkA  = tid >> 4;          // 0..7
    const int lofA = (tid & 15) << 2;   // 0..60
    const int lkB  = tid >> 5;          // 0..3
    const int lofB = (tid & 31) << 2;   // 0..124

    const uint32_t sA = (uint32_t)__cvta_generic_to_shared(&As[0][0][0]);
    const uint32_t sB = (uint32_t)__cvta_generic_to_shared(&Bs[0][0][0]);
    #define SA_ADDR(b, k, off) (sA + (uint32_t)(((b) * BK + (k)) * BM1 + (off)) * 4u)
    #define SB_ADDR(b, k, off) (sB + (uint32_t)(((b) * BK + (k)) * BN1 + (off)) * 4u)

    ull acc[4][8];
    #pragma unroll
    for (int i = 0; i < 4; i++)
        #pragma unroll
        for (int j = 0; j < 8; j++) acc[i][j] = 0ull;

    // prologue
    #pragma unroll
    for (int r = 0; r < BK; r += 8)
        cp_async16(SA_ADDR(0, lkA + r, lofA), &A[(size_t)(lkA + r) * lda + bm + lofA]);
    #pragma unroll
    for (int r = 0; r < BK; r += 4)
        cp_async16(SB_ADDR(0, lkB + r, lofB), &B[(size_t)(lkB + r) * ldb + bn + lofB]);
    cp_commit();
    cp_wait<0>();
    __syncthreads();

    int buf = 0;
    for (int iter = 0; iter < NITER; iter++) {
        if (iter + 1 < NITER) {
            const int kt = (iter + 1) * BK;
            const int nb = buf ^ 1;
            #pragma unroll
            for (int r = 0; r < BK; r += 8)
                cp_async16(SA_ADDR(nb, lkA + r, lofA), &A[(size_t)(kt + lkA + r) * lda + bm + lofA]);
            #pragma unroll
            for (int r = 0; r < BK; r += 4)
                cp_async16(SB_ADDR(nb, lkB + r, lofB), &B[(size_t)(kt + lkB + r) * ldb + bn + lofB]);
            cp_commit();
        }

        #pragma unroll
        for (int k = 0; k < BK; k++) {
            ulonglong2 av0 = *reinterpret_cast<const ulonglong2*>(&As[buf][k][ty]);
            ulonglong2 av1 = *reinterpret_cast<const ulonglong2*>(&As[buf][k][ty + 4]);
            float4 b0 = *reinterpret_cast<const float4*>(&Bs[buf][k][tx]);
            float4 b1 = *reinterpret_cast<const float4*>(&Bs[buf][k][tx + 64]);
            ull ap[4] = {av0.x, av0.y, av1.x, av1.y};
            ull bb[8];
            bb[0] = bcast2(b0.x); bb[1] = bcast2(b0.y);
            bb[2] = bcast2(b0.z); bb[3] = bcast2(b0.w);
            bb[4] = bcast2(b1.x); bb[5] = bcast2(b1.y);
            bb[6] = bcast2(b1.z); bb[7] = bcast2(b1.w);
            #pragma unroll
            for (int i = 0; i < 4; i++)
                #pragma unroll
                for (int j = 0; j < 8; j++)
                    ffma2(acc[i][j], ap[i], bb[j]);
        }

        if (iter + 1 < NITER) {
            cp_wait<0>();
            __syncthreads();
            buf ^= 1;
        }
    }

    // epilogue
    if (addBias) {
        float4 bv0 = *reinterpret_cast<const float4*>(&bias[bn + tx]);
        float4 bv1 = *reinterpret_cast<const float4*>(&bias[bn + tx + 64]);
        const float bb[8] = {bv0.x, bv0.y, bv0.z, bv0.w, bv1.x, bv1.y, bv1.z, bv1.w};
        #pragma unroll
        for (int i = 0; i < 4; i++) {
            #pragma unroll
            for (int half = 0; half < 2; half++) {
                int row = bm + ty + 2 * i + half;
                float4 p0 = *reinterpret_cast<const float4*>(&C[(size_t)row * N + bn + tx]);
                float4 p1 = *reinterpret_cast<const float4*>(&C[(size_t)row * N + bn + tx + 64]);
                float pr[8] = {p0.x, p0.y, p0.z, p0.w, p1.x, p1.y, p1.z, p1.w};
                float o[8];
                #pragma unroll
                for (int j = 0; j < 8; j++) {
                    float lo, hi;
                    unpack2(lo, hi, acc[i][j]);
                    float mine = half ? hi : lo;
                    o[j] = __fadd_rn(__fadd_rn(pr[j], mine), bb[j]);
                }
                float4 s0 = {o[0], o[1], o[2], o[3]};
                float4 s1 = {o[4], o[5], o[6], o[7]};
                *reinterpret_cast<float4*>(&C[(size_t)row * N + bn + tx]) = s0;
                *reinterpret_cast<float4*>(&C[(size_t)row * N + bn + tx + 64]) = s1;
            }
        }
    } else {
        #pragma unroll
        for (int i = 0; i < 4; i++) {
            float lo[8], hi[8];
            #pragma unroll
            for (int j = 0; j < 8; j++) unpack2(lo[j], hi[j], acc[i][j]);
            int r0 = bm + ty + 2 * i;
            float4 s0 = {lo[0], lo[1], lo[2], lo[3]};
            float4 s1 = {lo[4], lo[5], lo[6], lo[7]};
            float4 s2 = {hi[0], hi[1], hi[2], hi[3]};
            float4 s3 = {hi[4], hi[5], hi[6], hi[7]};
            *reinterpret_cast<float4*>(&C[(size_t)r0 * N + bn + tx]) = s0;
            *reinterpret_cast<float4*>(&C[(size_t)r0 * N + bn + tx + 64]) = s1;
            *reinterpret_cast<float4*>(&C[(size_t)(r0 + 1) * N + bn + tx]) = s2;
            *reinterpret_cast<float4*>(&C[(size_t)(r0 + 1) * N + bn + tx + 64]) = s3;
        }
    }
    #undef SA_ADDR
    #undef SB_ADDR
}

// ---------------------------------------------------------------------------
// GEMM2 panel (R14-proven): 64x128 tile, 128 threads, 4 CTAs/SM.
// A m-major (spk1): thread stages row (tid>>1), k-cols ((tid&1)*16..+15)
// and STS-transposes into As[k][row]. B k-major via cp.async.
// Same per-element numerics contract. Microtile 8m(4 m-pairs) x 8n.
// ---------------------------------------------------------------------------
__global__ __launch_bounds__(128, 4)
void sgemm2_panel(const float* __restrict__ A,
                  const float* __restrict__ B,
                  const float* __restrict__ bias,
                  float* __restrict__ C,
                  int lda, int ldb, int N, int addBias)
{
    __shared__ __align__(16) float As[2][BK][BM1];   // 16 KB
    __shared__ __align__(16) float Bs[2][BK][BN1];   // 32 KB

    const int tid = threadIdx.x;
    const int bm = blockIdx.y * BM1;
    const int bn = blockIdx.x * BN1;

    const int tx = (tid & 15) << 2;
    const int ty = (tid >> 4) << 3;

    const int lkB  = tid >> 5;          // 0..3
    const int lofB = (tid & 31) << 2;   // 0..124

    const int lr2  = tid >> 1;          // 0..63
    const int lc16 = (tid & 1) << 4;    // 0, 16

    const uint32_t sB = (uint32_t)__cvta_generic_to_shared(&Bs[0][0][0]);
    #define SB2_ADDR(b, k, off) (sB + (uint32_t)(((b) * BK + (k)) * BN1 + (off)) * 4u)

    ull acc[4][8];
    #pragma unroll
    for (int i = 0; i < 4; i++)
        #pragma unroll
        for (int j = 0; j < 8; j++) acc[i][j] = 0ull;

    // prologue
    #pragma unroll
    for (int r = 0; r < BK; r += 4)
        cp_async16(SB2_ADDR(0, lkB + r, lofB), &B[(size_t)(lkB + r) * ldb + bn + lofB]);
    #pragma unroll
    for (int q = 0; q < 4; q++) {
        float4 a = *reinterpret_cast<const float4*>(&A[(size_t)(bm + lr2) * lda + lc16 + 4 * q]);
        As[0][lc16 + 4 * q + 0][lr2] = a.x;
        As[0][lc16 + 4 * q + 1][lr2] = a.y;
        As[0][lc16 + 4 * q + 2][lr2] = a.z;
        As[0][lc16 + 4 * q + 3][lr2] = a.w;
    }
    cp_commit();
    cp_wait<0>();
    __syncthreads();

    int buf = 0;
    for (int iter = 0; iter < NITER; iter++) {
        float4 stA[4];
        if (iter + 1 < NITER) {
            const int kt = (iter + 1) * BK;
            const int nb = buf ^ 1;
            #pragma unroll
            for (int r = 0; r < BK; r += 4)
                cp_async16(SB2_ADDR(nb, lkB + r, lofB), &B[(size_t)(kt + lkB + r) * ldb + bn + lofB]);
            #pragma unroll
            for (int q = 0; q < 4; q++)
                stA[q] = *reinterpret_cast<const float4*>(&A[(size_t)(bm + lr2) * lda + kt + lc16 + 4 * q]);
            cp_commit();
        }

        #pragma unroll
        for (int k = 0; k < BK; k++) {
            ulonglong2 av0 = *reinterpret_cast<const ulonglong2*>(&As[buf][k][ty]);
            ulonglong2 av1 = *reinterpret_cast<const ulonglong2*>(&As[buf][k][ty + 4]);
            float4 b0 = *reinterpret_cast<const float4*>(&Bs[buf][k][tx]);
            float4 b1 = *reinterpret_cast<const float4*>(&Bs[buf][k][tx + 64]);
            ull ap[4] = {av0.x, av0.y, av1.x, av1.y};
            ull bb[8];
            bb[0] = bcast2(b0.x); bb[1] = bcast2(b0.y);
            bb[2] = bcast2(b0.z); bb[3] = bcast2(b0.w);
            bb[4] = bcast2(b1.x); bb[5] = bcast2(b1.y);
            bb[6] = bcast2(b1.z); bb[7] = bcast2(b1.w);
            #pragma unroll
            for (int i = 0; i < 4; i++)
                #pragma unroll
                for (int j = 0; j < 8; j++)
                    ffma2(acc[i][j], ap[i], bb[j]);
        }

        if (iter + 1 < NITER) {
            const int nb = buf ^ 1;
            #pragma unroll
            for (int q = 0; q < 4; q++) {
                As[nb][lc16 + 4 * q + 0][lr2] = stA[q].x;
                As[nb][lc16 + 4 * q + 1][lr2] = stA[q].y;
                As[nb][lc16 + 4 * q + 2][lr2] = stA[q].z;
                As[nb][lc16 + 4 * q + 3][lr2] = stA[q].w;
            }
            cp_wait<0>();
            __syncthreads();
            buf = nb;
        }
    }

    // epilogue
    if (addBias) {
        float4 bv0 = *reinterpret_cast<const float4*>(&bias[bn + tx]);
        float4 bv1 = *reinterpret_cast<const float4*>(&bias[bn + tx + 64]);
        const float bb[8] = {bv0.x, bv0.y, bv0.z, bv0.w, bv1.x, bv1.y, bv1.z, bv1.w};
        #pragma unroll
        for (int i = 0; i < 4; i++) {
            #pragma unroll
            for (int half = 0; half < 2; half++) {
                int row = bm + ty + 2 * i + half;
                float4 p0 = *reinterpret_cast<const float4*>(&C[(size_t)row * N + bn + tx]);
                float4 p1 = *reinterpret_cast<const float4*>(&C[(size_t)row * N + bn + tx + 64]);
                float pr[8] = {p0.x, p0.y, p0.z, p0.w, p1.x, p1.y, p1.z, p1.w};
                float o[8];
                #pragma unroll
                for (int j = 0; j < 8; j++) {
                    float lo, hi;
                    unpack2(lo, hi, acc[i][j]);
                    float mine = half ? hi : lo;
                    o[j] = __fadd_rn(__fadd_rn(pr[j], mine), bb[j]);
                }
                float4 s0 = {o[0], o[1], o[2], o[3]};
                float4 s1 = {o[4], o[5], o[6], o[7]};
                *reinterpret_cast<float4*>(&C[(size_t)row * N + bn + tx]) = s0;
                *reinterpret_cast<float4*>(&C[(size_t)row * N + bn + tx + 64]) = s1;
            }
        }
    } else {
        #pragma unroll
        for (int i = 0; i < 4; i++) {
            float lo[8], hi[8];
            #pragma unroll
            for (int j = 0; j < 8; j++) unpack2(lo[j], hi[j], acc[i][j]);
            int r0 = bm + ty + 2 * i;
            float4 s0 = {lo[0], lo[1], lo[2], lo[3]};
            float4 s1 = {lo[4], lo[5], lo[6], lo[7]};
            float4 s2 = {hi[0], hi[1], hi[2], hi[3]};
            float4 s3 = {hi[4], hi[5], hi[6], hi[7]};
            *reinterpret_cast<float4*>(&C[(size_t)r0 * N + bn + tx]) = s0;
            *reinterpret_cast<float4*>(&C[(size_t)r0 * N + bn + tx + 64]) = s1;
            *reinterpret_cast<float4*>(&C[(size_t)(r0 + 1) * N + bn + tx]) = s2;
            *reinterpret_cast<float4*>(&C[(size_t)(r0 + 1) * N + bn + tx + 64]) = s3;
        }
    }
    #undef SB2_ADDR
}

// ---------------------------------------------------------------------------
// LIF recurrence, XLA-exact op ordering per lane (no FMA contraction).
// Blocked prefetch: 4 independent LDGs in flight (MLP=4) ahead of each
// 4-step compute block. Per-lane arithmetic order unchanged -> bit-exact.
// ---------------------------------------------------------------------------
__device__ __forceinline__ void lif_step(float& mem, float& s, float c, float thr) {
    float t0 = __fmul_rn(BETA_F, mem);
    float t1 = __fadd_rn(t0, c);
    float t2 = __fmul_rn(s, thr);
    mem = __fsub_rn(t1, t2);
    s = (__fsub_rn(mem, thr) > 0.f) ? 1.0f : 0.0f;
}

__global__ void lif_scan1(const float* __restrict__ cur,
                          const float* __restrict__ thr_p,
                          float* __restrict__ spk_rec,
                          int stride)
{
    const int idx = blockIdx.x * blockDim.x + threadIdx.x;
    const float thr = *thr_p;
    float mem = 0.f, s = 0.f;
    const float* p = cur + idx;
    float* q = spk_rec + idx;

    float cb[4];
    #pragma unroll
    for (int i = 0; i < 4; i++) cb[i] = p[(size_t)i * stride];

    for (int t = 0; t < T_STEPS; t += 4) {
        float nb[4];
        if (t + 4 < T_STEPS) {
            #pragma unroll
            for (int i = 0; i < 4; i++) nb[i] = p[(size_t)(t + 4 + i) * stride];
        } else {
            #pragma unroll
            for (int i = 0; i < 4; i++) nb[i] = 0.f;
        }
        #pragma unroll
        for (int i = 0; i < 4; i++) {
            lif_step(mem, s, cb[i], thr);
            q[(size_t)(t + i) * stride] = s;
        }
        #pragma unroll
        for (int i = 0; i < 4; i++) cb[i] = nb[i];
    }
}

// ---------------------------------------------------------------------------
extern "C" void kernel_launch(void* const* d_in, const int* in_sizes, int n_in,
                              void* d_out, int out_size)
{
    const float* x    = (const float*)d_in[0];  // [T,B,I]
    const float* w1   = (const float*)d_in[1];  // [H,I]
    const float* b1   = (const float*)d_in[2];  // [H]
    const float* w2   = (const float*)d_in[3];  // [O,H]
    const float* b2   = (const float*)d_in[4];  // [O]
    const float* thr1 = (const float*)d_in[5];  // scalar
    const float* thr2 = (const float*)d_in[6];  // scalar

    float* out  = (float*)d_out;
    float* spk1 = out;                                    // [T,B,H]
    float* spk2 = out + (size_t)T_STEPS * BATCH * HID;    // [T,B,O]

    float *cur1, *cur2, *xT, *w1T, *w2T;
    cudaGetSymbolAddress((void**)&cur1, g_cur1);
    cudaGetSymbolAddress((void**)&cur2, g_cur2);
    cudaGetSymbolAddress((void**)&xT,  g_xT);
    cudaGetSymbolAddress((void**)&w1T, g_w1T);
    cudaGetSymbolAddress((void**)&w2T, g_w2T);

    // prep: bit-copy transposes to k-major layouts (launch idx 0-2;
    // GEMM1 phase0 lands at idx 3 = the ncu capture slot)
    transpose_v4<<<dim3(INDIM / 32, MROWS / 32), 256>>>(x, xT, MROWS, INDIM);
    transpose_v4<<<dim3(INDIM / 32, HID / 32), 256>>>(w1, w1T, HID, INDIM);
    transpose_v4<<<dim3(HID / 32, OUTDIM / 32), 256>>>(w2, w2T, OUTDIM, HID);

    // 1) cur1 = X @ W1^T + b1   (two kc=512 panels; 64x128 CTAs, 4/SM)
    {
        dim3 grid(HID / BN1, MROWS / BM1);   // (8, 512) = 4096 CTAs
        sgemm1_panel<<<grid, 128>>>(xT, w1T, b1, cur1, MROWS, HID, HID, 0);
        sgemm1_panel<<<grid, 128>>>(xT + (size_t)KC * MROWS, w1T + (size_t)KC * HID,
                                    b1, cur1, MROWS, HID, HID, 1);
    }
    // 2) LIF layer 1 -> spk1_rec
    lif_scan1<<<(BATCH * HID) / 256, 256>>>(cur1, thr1, spk1, BATCH * HID);

    // 3) cur2 = spk1_rec @ W2^T + b2   (64x128 CTAs, 4/SM, 1024 CTAs)
    {
        dim3 grid(OUTDIM / BN1, MROWS / BM1);  // (2, 512) = 1024 CTAs
        sgemm2_panel<<<grid, 128>>>(spk1, w2T, b2, cur2, HID, OUTDIM, OUTDIM, 0);
        sgemm2_panel<<<grid, 128>>>(spk1 + KC, w2T + (size_t)KC * OUTDIM,
                                    b2, cur2, HID, OUTDIM, OUTDIM, 1);
    }
    // 4) LIF layer 2 -> spk2_rec
    lif_scan1<<<(BATCH * OUTDIM) / 256, 256>>>(cur2, thr2, spk2, BATCH * OUTDIM);
}

// round 17
// speedup vs baseline: 1.0426x; 1.0287x over previous
#include <cuda_runtime.h>
#include <cstdint>

// Problem dims
#define T_STEPS 256
#define BATCH   128
#define INDIM   1024
#define HID     1024
#define OUTDIM  256
#define MROWS   (T_STEPS * BATCH)   // 32768
#define BETA_F  0.9f
#define KC      512                 // Eigen gebp panel depth (bit-exactness contract)

// Scratch (allocation-free rule: __device__ globals)
__device__ float g_cur1[(size_t)MROWS * HID];     // 128 MB
__device__ float g_cur2[(size_t)MROWS * OUTDIM];  // 32 MB
__device__ float g_xT  [(size_t)INDIM * MROWS];   // 128 MB  x transposed (k-major)
__device__ float g_w1T [(size_t)INDIM * HID];     // 4 MB    w1 transposed
__device__ float g_w2T [(size_t)HID * OUTDIM];    // 1 MB    w2 transposed

typedef unsigned long long ull;

// ---- packed f32x2 helpers (each lane = independent IEEE fp32 rn op) --------
__device__ __forceinline__ void ffma2(ull& d, ull a, ull b) {
    asm("fma.rn.f32x2 %0, %1, %2, %0;" : "+l"(d) : "l"(a), "l"(b));
}
__device__ __forceinline__ ull bcast2(float x) {
    ull r; asm("mov.b64 %0, {%1, %1};" : "=l"(r) : "f"(x)); return r;
}
__device__ __forceinline__ void unpack2(float& lo, float& hi, ull v) {
    asm("mov.b64 {%0, %1}, %2;" : "=f"(lo), "=f"(hi) : "l"(v));
}

// ---- cp.async helpers ------------------------------------------------------
__device__ __forceinline__ void cp_async16(uint32_t smem, const void* g) {
    asm volatile("cp.async.cg.shared.global [%0], [%1], 16;" :: "r"(smem), "l"(g));
}
__device__ __forceinline__ void cp_commit() {
    asm volatile("cp.async.commit_group;" ::: "memory");
}
template<int N>
__device__ __forceinline__ void cp_wait() {
    asm volatile("cp.async.wait_group %0;" :: "n"(N) : "memory");
}

// ---------------------------------------------------------------------------
// Vectorized tiled transpose: in [rows][cols] -> out [cols][rows]. Bit copy.
// ---------------------------------------------------------------------------
__global__ void transpose_v4(const float* __restrict__ in, float* __restrict__ out,
                             int rows, int cols)
{
    __shared__ float tile[32][33];
    const int c0 = blockIdx.x * 32;
    const int r0 = blockIdx.y * 32;
    const int tr = threadIdx.x >> 3;          // 0..31
    const int tc = (threadIdx.x & 7) << 2;    // 0,4,...,28

    float4 v = *reinterpret_cast<const float4*>(&in[(size_t)(r0 + tr) * cols + c0 + tc]);
    tile[tr][tc + 0] = v.x; tile[tr][tc + 1] = v.y;
    tile[tr][tc + 2] = v.z; tile[tr][tc + 3] = v.w;
    __syncthreads();

    float4 o;
    o.x = tile[tc + 0][tr]; o.y = tile[tc + 1][tr];
    o.z = tile[tc + 2][tr]; o.w = tile[tc + 3][tr];
    *reinterpret_cast<float4*>(&out[(size_t)(c0 + tr) * rows + r0 + tc]) = o;
}

#define BK 32
#define NITER (KC / BK)   // 16
#define BM1 64
#define BN1 128

// ---------------------------------------------------------------------------
// GEMM1 panel (kc=512): A,B k-major, cp.async, 2-stage, BK=32.
// 64x128 tile, 128 threads. EXPERIMENT: __launch_bounds__(128,3) gives ptxas
// up to 170 regs to hoist next-k LDS operands (was capped at exactly 128,
// leaving zero headroom for software pipelining of the inner loop).
// Numerics contract (bit-match Eigen gebp kc=512, VERIFIED rel_err==0):
//   per element: S = fadd( chain(k=0..511), chain(k=512..1023) ), chains are
//   ascending-k fp32 FMA chains from 0; then ONE rounded bias add (phase 1).
// Microtile 8m(4 f32x2 m-pairs) x 8n per thread.
// ---------------------------------------------------------------------------
__global__ __launch_bounds__(128, 3)
void sgemm1_panel(const float* __restrict__ A,
                  const float* __restrict__ B,
                  const float* __restrict__ bias,
                  float* __restrict__ C,
                  int lda, int ldb, int N, int addBias)
{
    __shared__ __align__(16) float As[2][BK][BM1];   // 16 KB
    __shared__ __align__(16) float Bs[2][BK][BN1];   // 32 KB

    const int tid = threadIdx.x;
    const int bm = blockIdx.y * BM1;
    const int bn = blockIdx.x * BN1;

    const int tx = (tid & 15) << 2;   // n base (4 wide); second group at +64
    const int ty = (tid >> 4) << 3;   // m base (8 tall, consecutive)

    const int lkA  = tid >> 4;          // 0..7
    const int lofA = (tid & 15) << 2;   // 0..60
    const int lkB  = tid >> 5;          // 0..3
    const int lofB = (tid & 31) << 2;   // 0..124

    const uint32_t sA = (uint32_t)__cvta_generic_to_shared(&As[0][0][0]);
    const uint32_t sB = (uint32_t)__cvta_generic_to_shared(&Bs[0][0][0]);
    #define SA_ADDR(b, k, off) (sA + (uint32_t)(((b) * BK + (k)) * BM1 + (off)) * 4u)
    #define SB_ADDR(b, k, off) (sB + (uint32_t)(((b) * BK + (k)) * BN1 + (off)) * 4u)

    ull acc[4][8];
    #pragma unroll
    for (int i = 0; i < 4; i++)
        #pragma unroll
        for (int j = 0; j < 8; j++) acc[i][j] = 0ull;

    // prologue
    #pragma unroll
    for (int r = 0; r < BK; r += 8)
        cp_async16(SA_ADDR(0, lkA + r, lofA), &A[(size_t)(lkA + r) * lda + bm + lofA]);
    #pragma unroll
    for (int r = 0; r < BK; r += 4)
        cp_async16(SB_ADDR(0, lkB + r, lofB), &B[(size_t)(lkB + r) * ldb + bn + lofB]);
    cp_commit();
    cp_wait<0>();
    __syncthreads();

    int buf = 0;
    for (int iter = 0; iter < NITER; iter++) {
        if (iter + 1 < NITER) {
            const int kt = (iter + 1) * BK;
            const int nb = buf ^ 1;
            #pragma unroll
            for (int r = 0; r < BK; r += 8)
                cp_async16(SA_ADDR(nb, lkA + r, lofA), &A[(size_t)(kt + lkA + r) * lda + bm + lofA]);
            #pragma unroll
            for (int r = 0; r < BK; r += 4)
                cp_async16(SB_ADDR(nb, lkB + r, lofB), &B[(size_t)(kt + lkB + r) * ldb + bn + lofB]);
            cp_commit();
        }

        #pragma unroll
        for (int k = 0; k < BK; k++) {
            ulonglong2 av0 = *reinterpret_cast<const ulonglong2*>(&As[buf][k][ty]);
            ulonglong2 av1 = *reinterpret_cast<const ulonglong2*>(&As[buf][k][ty + 4]);
            float4 b0 = *reinterpret_cast<const float4*>(&Bs[buf][k][tx]);
            float4 b1 = *reinterpret_cast<const float4*>(&Bs[buf][k][tx + 64]);
            ull ap[4] = {av0.x, av0.y, av1.x, av1.y};
            ull bb[8];
            bb[0] = bcast2(b0.x); bb[1] = bcast2(b0.y);
            bb[2] = bcast2(b0.z); bb[3] = bcast2(b0.w);
            bb[4] = bcast2(b1.x); bb[5] = bcast2(b1.y);
            bb[6] = bcast2(b1.z); bb[7] = bcast2(b1.w);
            #pragma unroll
            for (int i = 0; i < 4; i++)
                #pragma unroll
                for (int j = 0; j < 8; j++)
                    ffma2(acc[i][j], ap[i], bb[j]);
        }

        if (iter + 1 < NITER) {
            cp_wait<0>();
            __syncthreads();
            buf ^= 1;
        }
    }

    // epilogue
    if (addBias) {
        float4 bv0 = *reinterpret_cast<const float4*>(&bias[bn + tx]);
        float4 bv1 = *reinterpret_cast<const float4*>(&bias[bn + tx + 64]);
        const float bb[8] = {bv0.x, bv0.y, bv0.z, bv0.w, bv1.x, bv1.y, bv1.z, bv1.w};
        #pragma unroll
        for (int i = 0; i < 4; i++) {
            #pragma unroll
            for (int half = 0; half < 2; half++) {
                int row = bm + ty + 2 * i + half;
                float4 p0 = *reinterpret_cast<const float4*>(&C[(size_t)row * N + bn + tx]);
                float4 p1 = *reinterpret_cast<const float4*>(&C[(size_t)row * N + bn + tx + 64]);
                float pr[8] = {p0.x, p0.y, p0.z, p0.w, p1.x, p1.y, p1.z, p1.w};
                float o[8];
                #pragma unroll
                for (int j = 0; j < 8; j++) {
                    float lo, hi;
                    unpack2(lo, hi, acc[i][j]);
                    float mine = half ? hi : lo;
                    o[j] = __fadd_rn(__fadd_rn(pr[j], mine), bb[j]);
                }
                float4 s0 = {o[0], o[1], o[2], o[3]};
                float4 s1 = {o[4], o[5], o[6], o[7]};
                *reinterpret_cast<float4*>(&C[(size_t)row * N + bn + tx]) = s0;
                *reinterpret_cast<float4*>(&C[(size_t)row * N + bn + tx + 64]) = s1;
            }
        }
    } else {
        #pragma unroll
        for (int i = 0; i < 4; i++) {
            float lo[8], hi[8];
            #pragma unroll
            for (int j = 0; j < 8; j++) unpack2(lo[j], hi[j], acc[i][j]);
            int r0 = bm + ty + 2 * i;
            float4 s0 = {lo[0], lo[1], lo[2], lo[3]};
            float4 s1 = {lo[4], lo[5], lo[6], lo[7]};
            float4 s2 = {hi[0], hi[1], hi[2], hi[3]};
            float4 s3 = {hi[4], hi[5], hi[6], hi[7]};
            *reinterpret_cast<float4*>(&C[(size_t)r0 * N + bn + tx]) = s0;
            *reinterpret_cast<float4*>(&C[(size_t)r0 * N + bn + tx + 64]) = s1;
            *reinterpret_cast<float4*>(&C[(size_t)(r0 + 1) * N + bn + tx]) = s2;
            *reinterpret_cast<float4*>(&C[(size_t)(r0 + 1) * N + bn + tx + 64]) = s3;
        }
    }
    #undef SA_ADDR
    #undef SB_ADDR
}

// ---------------------------------------------------------------------------
// GEMM2 panel (R14-proven, UNCHANGED occ hedge): 64x128 tile, 128 threads,
// 4 CTAs/SM. A m-major (spk1) staged via LDG+STS; B k-major via cp.async.
// Same per-element numerics contract. Microtile 8m(4 m-pairs) x 8n.
// ---------------------------------------------------------------------------
__global__ __launch_bounds__(128, 4)
void sgemm2_panel(const float* __restrict__ A,
                  const float* __restrict__ B,
                  const float* __restrict__ bias,
                  float* __restrict__ C,
                  int lda, int ldb, int N, int addBias)
{
    __shared__ __align__(16) float As[2][BK][BM1];   // 16 KB
    __shared__ __align__(16) float Bs[2][BK][BN1];   // 32 KB

    const int tid = threadIdx.x;
    const int bm = blockIdx.y * BM1;
    const int bn = blockIdx.x * BN1;

    const int tx = (tid & 15) << 2;
    const int ty = (tid >> 4) << 3;

    const int lkB  = tid >> 5;          // 0..3
    const int lofB = (tid & 31) << 2;   // 0..124

    const int lr2  = tid >> 1;          // 0..63
    const int lc16 = (tid & 1) << 4;    // 0, 16

    const uint32_t sB = (uint32_t)__cvta_generic_to_shared(&Bs[0][0][0]);
    #define SB2_ADDR(b, k, off) (sB + (uint32_t)(((b) * BK + (k)) * BN1 + (off)) * 4u)

    ull acc[4][8];
    #pragma unroll
    for (int i = 0; i < 4; i++)
        #pragma unroll
        for (int j = 0; j < 8; j++) acc[i][j] = 0ull;

    // prologue
    #pragma unroll
    for (int r = 0; r < BK; r += 4)
        cp_async16(SB2_ADDR(0, lkB + r, lofB), &B[(size_t)(lkB + r) * ldb + bn + lofB]);
    #pragma unroll
    for (int q = 0; q < 4; q++) {
        float4 a = *reinterpret_cast<const float4*>(&A[(size_t)(bm + lr2) * lda + lc16 + 4 * q]);
        As[0][lc16 + 4 * q + 0][lr2] = a.x;
        As[0][lc16 + 4 * q + 1][lr2] = a.y;
        As[0][lc16 + 4 * q + 2][lr2] = a.z;
        As[0][lc16 + 4 * q + 3][lr2] = a.w;
    }
    cp_commit();
    cp_wait<0>();
    __syncthreads();

    int buf = 0;
    for (int iter = 0; iter < NITER; iter++) {
        float4 stA[4];
        if (iter + 1 < NITER) {
            const int kt = (iter + 1) * BK;
            const int nb = buf ^ 1;
            #pragma unroll
            for (int r = 0; r < BK; r += 4)
                cp_async16(SB2_ADDR(nb, lkB + r, lofB), &B[(size_t)(kt + lkB + r) * ldb + bn + lofB]);
            #pragma unroll
            for (int q = 0; q < 4; q++)
                stA[q] = *reinterpret_cast<const float4*>(&A[(size_t)(bm + lr2) * lda + kt + lc16 + 4 * q]);
            cp_commit();
        }

        #pragma unroll
        for (int k = 0; k < BK; k++) {
            ulonglong2 av0 = *reinterpret_cast<const ulonglong2*>(&As[buf][k][ty]);
            ulonglong2 av1 = *reinterpret_cast<const ulonglong2*>(&As[buf][k][ty + 4]);
            float4 b0 = *reinterpret_cast<const float4*>(&Bs[buf][k][tx]);
            float4 b1 = *reinterpret_cast<const float4*>(&Bs[buf][k][tx + 64]);
            ull ap[4] = {av0.x, av0.y, av1.x, av1.y};
            ull bb[8];
            bb[0] = bcast2(b0.x); bb[1] = bcast2(b0.y);
            bb[2] = bcast2(b0.z); bb[3] = bcast2(b0.w);
            bb[4] = bcast2(b1.x); bb[5] = bcast2(b1.y);
            bb[6] = bcast2(b1.z); bb[7] = bcast2(b1.w);
            #pragma unroll
            for (int i = 0; i < 4; i++)
                #pragma unroll
                for (int j = 0; j < 8; j++)
                    ffma2(acc[i][j], ap[i], bb[j]);
        }

        if (iter + 1 < NITER) {
            const int nb = buf ^ 1;
            #pragma unroll
            for (int q = 0; q < 4; q++) {
                As[nb][lc16 + 4 * q + 0][lr2] = stA[q].x;
                As[nb][lc16 + 4 * q + 1][lr2] = stA[q].y;
                As[nb][lc16 + 4 * q + 2][lr2] = stA[q].z;
                As[nb][lc16 + 4 * q + 3][lr2] = stA[q].w;
            }
            cp_wait<0>();
            __syncthreads();
            buf = nb;
        }
    }

    // epilogue
    if (addBias) {
        float4 bv0 = *reinterpret_cast<const float4*>(&bias[bn + tx]);
        float4 bv1 = *reinterpret_cast<const float4*>(&bias[bn + tx + 64]);
        const float bb[8] = {bv0.x, bv0.y, bv0.z, bv0.w, bv1.x, bv1.y, bv1.z, bv1.w};
        #pragma unroll
        for (int i = 0; i < 4; i++) {
            #pragma unroll
            for (int half = 0; half < 2; half++) {
                int row = bm + ty + 2 * i + half;
                float4 p0 = *reinterpret_cast<const float4*>(&C[(size_t)row * N + bn + tx]);
                float4 p1 = *reinterpret_cast<const float4*>(&C[(size_t)row * N + bn + tx + 64]);
                float pr[8] = {p0.x, p0.y, p0.z, p0.w, p1.x, p1.y, p1.z, p1.w};
                float o[8];
                #pragma unroll
                for (int j = 0; j < 8; j++) {
                    float lo, hi;
                    unpack2(lo, hi, acc[i][j]);
                    float mine = half ? hi : lo;
                    o[j] = __fadd_rn(__fadd_rn(pr[j], mine), bb[j]);
                }
                float4 s0 = {o[0], o[1], o[2], o[3]};
                float4 s1 = {o[4], o[5], o[6], o[7]};
                *reinterpret_cast<float4*>(&C[(size_t)row * N + bn + tx]) = s0;
                *reinterpret_cast<float4*>(&C[(size_t)row * N + bn + tx + 64]) = s1;
            }
        }
    } else {
        #pragma unroll
        for (int i = 0; i < 4; i++) {
            float lo[8], hi[8];
            #pragma unroll
            for (int j = 0; j < 8; j++) unpack2(lo[j], hi[j], acc[i][j]);
            int r0 = bm + ty + 2 * i;
            float4 s0 = {lo[0], lo[1], lo[2], lo[3]};
            float4 s1 = {lo[4], lo[5], lo[6], lo[7]};
            float4 s2 = {hi[0], hi[1], hi[2], hi[3]};
            float4 s3 = {hi[4], hi[5], hi[6], hi[7]};
            *reinterpret_cast<float4*>(&C[(size_t)r0 * N + bn + tx]) = s0;
            *reinterpret_cast<float4*>(&C[(size_t)r0 * N + bn + tx + 64]) = s1;
            *reinterpret_cast<float4*>(&C[(size_t)(r0 + 1) * N + bn + tx]) = s2;
            *reinterpret_cast<float4*>(&C[(size_t)(r0 + 1) * N + bn + tx + 64]) = s3;
        }
    }
    #undef SB2_ADDR
}

// ---------------------------------------------------------------------------
// LIF recurrence, XLA-exact op ordering per lane (no FMA contraction).
// Blocked prefetch: 4 independent LDGs in flight (MLP=4).
// ---------------------------------------------------------------------------
__device__ __forceinline__ void lif_step(float& mem, float& s, float c, float thr) {
    float t0 = __fmul_rn(BETA_F, mem);
    float t1 = __fadd_rn(t0, c);
    float t2 = __fmul_rn(s, thr);
    mem = __fsub_rn(t1, t2);
    s = (__fsub_rn(mem, thr) > 0.f) ? 1.0f : 0.0f;
}

__global__ void lif_scan1(const float* __restrict__ cur,
                          const float* __restrict__ thr_p,
                          float* __restrict__ spk_rec,
                          int stride)
{
    const int idx = blockIdx.x * blockDim.x + threadIdx.x;
    const float thr = *thr_p;
    float mem = 0.f, s = 0.f;
    const float* p = cur + idx;
    float* q = spk_rec + idx;

    float cb[4];
    #pragma unroll
    for (int i = 0; i < 4; i++) cb[i] = p[(size_t)i * stride];

    for (int t = 0; t < T_STEPS; t += 4) {
        float nb[4];
        if (t + 4 < T_STEPS) {
            #pragma unroll
            for (int i = 0; i < 4; i++) nb[i] = p[(size_t)(t + 4 + i) * stride];
        } else {
            #pragma unroll
            for (int i = 0; i < 4; i++) nb[i] = 0.f;
        }
        #pragma unroll
        for (int i = 0; i < 4; i++) {
            lif_step(mem, s, cb[i], thr);
            q[(size_t)(t + i) * stride] = s;
        }
        #pragma unroll
        for (int i = 0; i < 4; i++) cb[i] = nb[i];
    }
}

// ---------------------------------------------------------------------------
extern "C" void kernel_launch(void* const* d_in, const int* in_sizes, int n_in,
                              void* d_out, int out_size)
{
    const float* x    = (const float*)d_in[0];  // [T,B,I]
    const float* w1   = (const float*)d_in[1];  // [H,I]
    const float* b1   = (const float*)d_in[2];  // [H]
    const float* w2   = (const float*)d_in[3];  // [O,H]
    const float* b2   = (const float*)d_in[4];  // [O]
    const float* thr1 = (const float*)d_in[5];  // scalar
    const float* thr2 = (const float*)d_in[6];  // scalar

    float* out  = (float*)d_out;
    float* spk1 = out;                                    // [T,B,H]
    float* spk2 = out + (size_t)T_STEPS * BATCH * HID;    // [T,B,O]

    float *cur1, *cur2, *xT, *w1T, *w2T;
    cudaGetSymbolAddress((void**)&cur1, g_cur1);
    cudaGetSymbolAddress((void**)&cur2, g_cur2);
    cudaGetSymbolAddress((void**)&xT,  g_xT);
    cudaGetSymbolAddress((void**)&w1T, g_w1T);
    cudaGetSymbolAddress((void**)&w2T, g_w2T);

    // prep: bit-copy transposes to k-major layouts (launch idx 0-2;
    // GEMM1 phase0 lands at idx 3 = the ncu capture slot)
    transpose_v4<<<dim3(INDIM / 32, MROWS / 32), 256>>>(x, xT, MROWS, INDIM);
    transpose_v4<<<dim3(INDIM / 32, HID / 32), 256>>>(w1, w1T, HID, INDIM);
    transpose_v4<<<dim3(HID / 32, OUTDIM / 32), 256>>>(w2, w2T, OUTDIM, HID);

    // 1) cur1 = X @ W1^T + b1   (two kc=512 panels; 64x128 CTAs)
    {
        dim3 grid(HID / BN1, MROWS / BM1);   // (8, 512) = 4096 CTAs
        sgemm1_panel<<<grid, 128>>>(xT, w1T, b1, cur1, MROWS, HID, HID, 0);
        sgemm1_panel<<<grid, 128>>>(xT + (size_t)KC * MROWS, w1T + (size_t)KC * HID,
                                    b1, cur1, MROWS, HID, HID, 1);
    }
    // 2) LIF layer 1 -> spk1_rec
    lif_scan1<<<(BATCH * HID) / 256, 256>>>(cur1, thr1, spk1, BATCH * HID);

    // 3) cur2 = spk1_rec @ W2^T + b2   (64x128 CTAs, 4/SM, 1024 CTAs)
    {
        dim3 grid(OUTDIM / BN1, MROWS / BM1);  // (2, 512) = 1024 CTAs
        sgemm2_panel<<<grid, 128>>>(spk1, w2T, b2, cur2, HID, OUTDIM, OUTDIM, 0);
        sgemm2_panel<<<grid, 128>>>(spk1 + KC, w2T + (size_t)KC * OUTDIM,
                                    b2, cur2, HID, OUTDIM, OUTDIM, 1);
    }
    // 4) LIF layer 2 -> spk2_rec
    lif_scan1<<<(BATCH * OUTDIM) / 256, 256>>>(cur2, thr2, spk2, BATCH * OUTDIM);
}